// round 2
// baseline (speedup 1.0000x reference)
#include <cuda_runtime.h>
#include <cuda_bf16.h>
#include <math.h>

// Problem constants
#define NN 100000
#define NE 1600000

// -------- device scratch (no allocations allowed) --------
__device__ int   g_counts[NN];
__device__ int   g_rowptr[NN + 1];
__device__ int   g_cursor[NN];
__device__ int   g_cols[NE];
__device__ float g_vals[NE];
__device__ float g_bufA[(size_t)NN * 64];  // GEMM outputs (support)
__device__ float g_bufB[(size_t)NN * 64];  // SpMM outputs (hidden)
__device__ float g_pool[64];

// -------- init: zero histogram + pool accumulator --------
__global__ void init_kernel() {
    int i = blockIdx.x * blockDim.x + threadIdx.x;
    if (i < NN) g_counts[i] = 0;
    if (i < 64) g_pool[i] = 0.f;
}

// -------- histogram of row indices --------
__global__ void hist_kernel(const int* __restrict__ row) {
    int e = blockIdx.x * blockDim.x + threadIdx.x;
    if (e < NE) atomicAdd(&g_counts[row[e]], 1);
}

// -------- single-block exclusive scan over counts -> rowptr, cursor --------
__global__ void scan_kernel() {
    __shared__ int ssum[1024];
    const int CH = (NN + 1023) / 1024;  // 98
    int t = threadIdx.x;
    int base = t * CH;
    int s = 0;
    for (int i = 0; i < CH; i++) {
        int idx = base + i;
        if (idx < NN) s += g_counts[idx];
    }
    ssum[t] = s;
    __syncthreads();
    // Hillis-Steele inclusive scan
    for (int off = 1; off < 1024; off <<= 1) {
        int v = (t >= off) ? ssum[t - off] : 0;
        __syncthreads();
        ssum[t] += v;
        __syncthreads();
    }
    int run = (t == 0) ? 0 : ssum[t - 1];
    for (int i = 0; i < CH; i++) {
        int idx = base + i;
        if (idx < NN) {
            g_rowptr[idx] = run;
            g_cursor[idx] = run;
            run += g_counts[idx];
        }
    }
    if (t == 1023) g_rowptr[NN] = ssum[1023];
}

// -------- scatter edges into CSR order --------
__global__ void scatter_kernel(const int* __restrict__ row,
                               const int* __restrict__ col,
                               const float* __restrict__ val) {
    int e = blockIdx.x * blockDim.x + threadIdx.x;
    if (e < NE) {
        int p = atomicAdd(&g_cursor[row[e]], 1);
        g_cols[p] = col[e];
        g_vals[p] = val[e];
    }
}

// -------- GEMM1: x[N,256] @ W1[256,32] -> g_bufA[N,32] --------
// 256 threads, tile 128 rows x 32 cols, thread computes 4x4, K chunked by 16.
__global__ void gemm1_kernel(const float* __restrict__ x, const float* __restrict__ W) {
    __shared__ float Ws[256 * 32];
    __shared__ float xs[128 * 17];
    int t = threadIdx.x;
    int base = blockIdx.x * 128;

    for (int i = t; i < 256 * 32; i += 256) Ws[i] = W[i];

    float acc[4][4];
#pragma unroll
    for (int i = 0; i < 4; i++)
#pragma unroll
        for (int j = 0; j < 4; j++) acc[i][j] = 0.f;

    int cg = t & 7, rg = t >> 3;
    int c0 = cg * 4, r0 = rg * 4;

    for (int kk = 0; kk < 256; kk += 16) {
        __syncthreads();
#pragma unroll
        for (int i = 0; i < 8; i++) {
            int idx = t + i * 256;
            int r = idx >> 4, k = idx & 15;
            int gr = base + r;
            xs[r * 17 + k] = (gr < NN) ? x[gr * 256 + kk + k] : 0.f;
        }
        __syncthreads();
#pragma unroll
        for (int k = 0; k < 16; k++) {
            float xv[4];
#pragma unroll
            for (int i = 0; i < 4; i++) xv[i] = xs[(r0 + i) * 17 + k];
            float4 wv = *(const float4*)&Ws[(kk + k) * 32 + c0];
#pragma unroll
            for (int i = 0; i < 4; i++) {
                acc[i][0] += xv[i] * wv.x;
                acc[i][1] += xv[i] * wv.y;
                acc[i][2] += xv[i] * wv.z;
                acc[i][3] += xv[i] * wv.w;
            }
        }
    }
#pragma unroll
    for (int i = 0; i < 4; i++) {
        int gr = base + r0 + i;
        if (gr < NN) {
#pragma unroll
            for (int j = 0; j < 4; j++) g_bufA[(size_t)gr * 32 + c0 + j] = acc[i][j];
        }
    }
}

// -------- small GEMM: g_bufB[N,IN] @ W[IN,OUT] -> g_bufA[N,OUT] --------
// 256 threads, tile 128 rows; thread computes 4 rows x (OUT/8) cols.
template <int IN, int OUT>
__global__ void gemm_small_kernel(const float* __restrict__ W) {
    constexpr int C = OUT / 8;
    __shared__ float Ws[IN * OUT];
    __shared__ float xs[128 * (IN + 1)];
    int t = threadIdx.x;
    int base = blockIdx.x * 128;

    for (int i = t; i < IN * OUT; i += 256) Ws[i] = W[i];

    size_t gbase = (size_t)base * IN;
    for (int i = t; i < 128 * IN; i += 256) {
        int r = i / IN, k = i % IN;
        int gr = base + r;
        xs[r * (IN + 1) + k] = (gr < NN) ? g_bufB[gbase + i] : 0.f;
    }
    __syncthreads();

    int cg = t & 7, rg = t >> 3;
    int c0 = cg * C, r0 = rg * 4;

    float acc[4][C];
#pragma unroll
    for (int i = 0; i < 4; i++)
#pragma unroll
        for (int j = 0; j < C; j++) acc[i][j] = 0.f;

#pragma unroll 4
    for (int k = 0; k < IN; k++) {
        float xv[4];
#pragma unroll
        for (int i = 0; i < 4; i++) xv[i] = xs[(r0 + i) * (IN + 1) + k];
        float wv[C];
#pragma unroll
        for (int j = 0; j < C; j++) wv[j] = Ws[k * OUT + c0 + j];
#pragma unroll
        for (int i = 0; i < 4; i++)
#pragma unroll
            for (int j = 0; j < C; j++) acc[i][j] += xv[i] * wv[j];
    }
#pragma unroll
    for (int i = 0; i < 4; i++) {
        int gr = base + r0 + i;
        if (gr < NN) {
#pragma unroll
            for (int j = 0; j < C; j++) g_bufA[(size_t)gr * OUT + c0 + j] = acc[i][j];
        }
    }
}

// -------- SpMM: out[i,f] = relu(bias[f] + sum_e val*sup[col,f]) ; A -> B --------
// Group of G threads per node; lane f < F accumulates one feature.
template <int F, int G>
__global__ void spmm_kernel(const float* __restrict__ bias) {
    constexpr int GPB = 256 / G;
    int g = blockIdx.x * GPB + threadIdx.x / G;
    int lane = threadIdx.x % G;
    if (g >= NN || lane >= F) return;
    int s = g_rowptr[g];
    int e = g_rowptr[g + 1];
    const float* __restrict__ sup = g_bufA;
    float acc = 0.f;
    for (int i = s; i < e; i++) {
        int c = __ldg(&g_cols[i]);
        float v = __ldg(&g_vals[i]);
        acc += v * __ldg(&sup[(size_t)c * F + lane]);
    }
    g_bufB[(size_t)g * F + lane] = fmaxf(acc + __ldg(&bias[lane]), 0.f);
}

// -------- global mean pool over g_bufB[N,64] -> g_pool[64] (sum; divide later) --------
__global__ void pool_kernel() {
    int f = threadIdx.x & 63;
    float s = 0.f;
    size_t total = (size_t)NN * 64;
    size_t stride = (size_t)gridDim.x * blockDim.x;  // multiple of 64
    for (size_t i = (size_t)blockIdx.x * blockDim.x + threadIdx.x; i < total; i += stride)
        s += g_bufB[i];
    atomicAdd(&g_pool[f], s);
}

// -------- head: mean -> fc1+relu -> fc2 -> softmax --------
__global__ void head_kernel(const float* __restrict__ f1W, const float* __restrict__ f1b,
                            const float* __restrict__ f2W, const float* __restrict__ f2b,
                            float* __restrict__ out) {
    __shared__ float y[64];
    __shared__ float a[32];
    __shared__ float l[2];
    int t = threadIdx.x;
    y[t] = g_pool[t] * (1.0f / NN);
    __syncthreads();
    if (t < 32) {
        float s = f1b[t];
#pragma unroll
        for (int k = 0; k < 64; k++) s += y[k] * f1W[k * 32 + t];
        a[t] = fmaxf(s, 0.f);
    }
    __syncthreads();
    if (t < 2) {
        float s = f2b[t];
#pragma unroll
        for (int j = 0; j < 32; j++) s += a[j] * f2W[j * 2 + t];
        l[t] = s;
    }
    __syncthreads();
    if (t == 0) {
        float m = fmaxf(l[0], l[1]);
        float e0 = expf(l[0] - m), e1 = expf(l[1] - m);
        float inv = 1.0f / (e0 + e1);
        out[0] = e0 * inv;
        out[1] = e1 * inv;
    }
}

extern "C" void kernel_launch(void* const* d_in, const int* in_sizes, int n_in,
                              void* d_out, int out_size) {
    (void)in_sizes; (void)n_in; (void)out_size;
    const float* x   = (const float*)d_in[0];
    const int*   row = (const int*)d_in[1];
    const int*   col = (const int*)d_in[2];
    const float* ev  = (const float*)d_in[3];
    const float* W1  = (const float*)d_in[4];
    const float* b1  = (const float*)d_in[5];
    const float* W2  = (const float*)d_in[6];
    const float* b2  = (const float*)d_in[7];
    const float* W3  = (const float*)d_in[8];
    const float* b3  = (const float*)d_in[9];
    const float* f1W = (const float*)d_in[10];
    const float* f1b = (const float*)d_in[11];
    const float* f2W = (const float*)d_in[12];
    const float* f2b = (const float*)d_in[13];
    float* out = (float*)d_out;

    const int EB = (NE + 255) / 256;        // 6250
    const int GB = (NN + 127) / 128;        // 782

    // CSR build (per-call, deterministic work)
    init_kernel<<<(NN + 255) / 256, 256>>>();
    hist_kernel<<<EB, 256>>>(row);
    scan_kernel<<<1, 1024>>>();
    scatter_kernel<<<EB, 256>>>(row, col, ev);

    // Layer 1: x@W1 -> A ; spmm(A)+b1,relu -> B   [F=32]
    gemm1_kernel<<<GB, 256>>>(x, W1);
    spmm_kernel<32, 32><<<(NN + 7) / 8, 256>>>(b1);

    // Layer 2: B@W2 -> A ; spmm(A)+b2,relu -> B   [F=48]
    gemm_small_kernel<32, 48><<<GB, 256>>>(W2);
    spmm_kernel<48, 64><<<(NN + 3) / 4, 256>>>(b2);

    // Layer 3: B@W3 -> A ; spmm(A)+b3,relu -> B   [F=64]
    gemm_small_kernel<48, 64><<<GB, 256>>>(W3);
    spmm_kernel<64, 64><<<(NN + 3) / 4, 256>>>(b3);

    // Pool + head
    pool_kernel<<<512, 256>>>();
    head_kernel<<<1, 64>>>(f1W, f1b, f2W, f2b, out);
}

// round 3
// speedup vs baseline: 1.8293x; 1.8293x over previous
#include <cuda_runtime.h>
#include <cuda_bf16.h>
#include <math.h>

#define NN 100000
#define NE 1600000

// -------- device scratch --------
__device__ int   g_counts[NN];
__device__ int   g_rowptr[NN + 1];
__device__ int   g_cursor[NN];
__device__ int   g_part[98];
__device__ int   g_partoff[98];
__device__ int2  g_edge[NE];               // {col, float_bits(val)}
__device__ float g_bufA[(size_t)NN * 64];
__device__ float g_bufB[(size_t)NN * 64];
__device__ float g_pool[64];

// -------- init --------
__global__ void init_kernel() {
    int i = blockIdx.x * blockDim.x + threadIdx.x;
    if (i < NN) g_counts[i] = 0;
    if (i < 64) g_pool[i] = 0.f;
}

// -------- histogram --------
__global__ void hist_kernel(const int* __restrict__ row) {
    int e = blockIdx.x * blockDim.x + threadIdx.x;
    if (e < NE) atomicAdd(&g_counts[row[e]], 1);
}

// -------- 3-phase scan: counts -> rowptr/cursor --------
__global__ void scan_phase1() {   // <<<98,1024>>>
    __shared__ int s[1024];
    int t = threadIdx.x;
    int idx = blockIdx.x * 1024 + t;
    int c = (idx < NN) ? g_counts[idx] : 0;
    s[t] = c;
    __syncthreads();
    for (int off = 1; off < 1024; off <<= 1) {
        int v = (t >= off) ? s[t - off] : 0;
        __syncthreads();
        s[t] += v;
        __syncthreads();
    }
    if (idx < NN) g_rowptr[idx] = s[t] - c;      // block-local exclusive
    if (t == 1023) g_part[blockIdx.x] = s[1023];
}

__global__ void scan_phase2() {   // <<<1,128>>>
    __shared__ int s[128];
    int t = threadIdx.x;
    int p = (t < 98) ? g_part[t] : 0;
    s[t] = p;
    __syncthreads();
    for (int off = 1; off < 128; off <<= 1) {
        int v = (t >= off) ? s[t - off] : 0;
        __syncthreads();
        s[t] += v;
        __syncthreads();
    }
    if (t < 98) g_partoff[t] = s[t] - p;
}

__global__ void scan_phase3() {   // <<<98,1024>>>
    int t = threadIdx.x;
    int idx = blockIdx.x * 1024 + t;
    if (idx < NN) {
        int r = g_rowptr[idx] + g_partoff[blockIdx.x];
        g_rowptr[idx] = r;
        g_cursor[idx] = r;
    }
    if (idx == 0) g_rowptr[NN] = NE;
}

// -------- scatter edges into CSR order (packed 8B) --------
__global__ void scatter_kernel(const int* __restrict__ row,
                               const int* __restrict__ col,
                               const float* __restrict__ val) {
    int e = blockIdx.x * blockDim.x + threadIdx.x;
    if (e < NE) {
        int p = atomicAdd(&g_cursor[row[e]], 1);
        int2 m;
        m.x = col[e];
        m.y = __float_as_int(val[e]);
        g_edge[p] = m;
    }
}

// -------- GEMM1: x[N,256] @ W1[256,32] -> g_bufA[N,32] --------
__global__ void gemm1_kernel(const float* __restrict__ x, const float* __restrict__ W) {
    __shared__ float Ws[256 * 32];
    __shared__ float xs[128 * 17];
    int t = threadIdx.x;
    int base = blockIdx.x * 128;

    for (int i = t; i < 256 * 32; i += 256) Ws[i] = W[i];

    float acc[4][4];
#pragma unroll
    for (int i = 0; i < 4; i++)
#pragma unroll
        for (int j = 0; j < 4; j++) acc[i][j] = 0.f;

    int cg = t & 7, rg = t >> 3;
    int c0 = cg * 4, r0 = rg * 4;

    for (int kk = 0; kk < 256; kk += 16) {
        __syncthreads();
        // 128 rows x 16 k = 512 float4; 2 per thread
#pragma unroll
        for (int j = 0; j < 2; j++) {
            int i4 = t + j * 256;
            int r = i4 >> 2, kq = i4 & 3;   // 4 float4 per row-chunk
            int gr = base + r;
            float4 v = (gr < NN) ? *(const float4*)&x[(size_t)gr * 256 + kk + kq * 4]
                                 : make_float4(0.f, 0.f, 0.f, 0.f);
            xs[r * 17 + kq * 4 + 0] = v.x;
            xs[r * 17 + kq * 4 + 1] = v.y;
            xs[r * 17 + kq * 4 + 2] = v.z;
            xs[r * 17 + kq * 4 + 3] = v.w;
        }
        __syncthreads();
#pragma unroll
        for (int k = 0; k < 16; k++) {
            float xv[4];
#pragma unroll
            for (int i = 0; i < 4; i++) xv[i] = xs[(r0 + i) * 17 + k];
            float4 wv = *(const float4*)&Ws[(kk + k) * 32 + c0];
#pragma unroll
            for (int i = 0; i < 4; i++) {
                acc[i][0] += xv[i] * wv.x;
                acc[i][1] += xv[i] * wv.y;
                acc[i][2] += xv[i] * wv.z;
                acc[i][3] += xv[i] * wv.w;
            }
        }
    }
#pragma unroll
    for (int i = 0; i < 4; i++) {
        int gr = base + r0 + i;
        if (gr < NN) {
            float4 o = make_float4(acc[i][0], acc[i][1], acc[i][2], acc[i][3]);
            *(float4*)&g_bufA[(size_t)gr * 32 + c0] = o;
        }
    }
}

// -------- small GEMM: g_bufA[N,IN] @ W[IN,OUT] (+bias, relu) -> g_bufB[N,OUT] --------
// Optionally fuses global mean-pool partial sums into g_pool.
template <int IN, int OUT, bool POOL>
__global__ void gemm_small_kernel(const float* __restrict__ W, const float* __restrict__ bias) {
    constexpr int C = OUT / 8;
    __shared__ float Ws[IN * OUT];
    __shared__ float xs[128 * (IN + 1)];
    __shared__ float spool[OUT];
    int t = threadIdx.x;
    int base = blockIdx.x * 128;

    for (int i = t; i < IN * OUT; i += 256) Ws[i] = W[i];
    if (POOL && t < OUT) spool[t] = 0.f;

    // vectorized load of 128 x IN source rows
    constexpr int NV = 128 * IN / 4;
    const float4* src4 = (const float4*)g_bufA;
    for (int i4 = t; i4 < NV; i4 += 256) {
        int r = i4 / (IN / 4), kq = i4 % (IN / 4);
        int gr = base + r;
        float4 v = (gr < NN) ? src4[(size_t)gr * (IN / 4) + kq]
                             : make_float4(0.f, 0.f, 0.f, 0.f);
        xs[r * (IN + 1) + kq * 4 + 0] = v.x;
        xs[r * (IN + 1) + kq * 4 + 1] = v.y;
        xs[r * (IN + 1) + kq * 4 + 2] = v.z;
        xs[r * (IN + 1) + kq * 4 + 3] = v.w;
    }
    __syncthreads();

    int cg = t & 7, rg = t >> 3;
    int c0 = cg * C, r0 = rg * 4;

    float acc[4][C];
#pragma unroll
    for (int i = 0; i < 4; i++)
#pragma unroll
        for (int j = 0; j < C; j++) acc[i][j] = 0.f;

#pragma unroll 4
    for (int k = 0; k < IN; k++) {
        float xv[4];
#pragma unroll
        for (int i = 0; i < 4; i++) xv[i] = xs[(r0 + i) * (IN + 1) + k];
        float wv[C];
#pragma unroll
        for (int j = 0; j < C; j++) wv[j] = Ws[k * OUT + c0 + j];
#pragma unroll
        for (int i = 0; i < 4; i++)
#pragma unroll
            for (int j = 0; j < C; j++) acc[i][j] += xv[i] * wv[j];
    }

    float colsum[C];
#pragma unroll
    for (int j = 0; j < C; j++) colsum[j] = 0.f;

#pragma unroll
    for (int i = 0; i < 4; i++) {
        int gr = base + r0 + i;
        if (gr < NN) {
#pragma unroll
            for (int j = 0; j < C; j++) {
                float v = fmaxf(acc[i][j] + bias[c0 + j], 0.f);
                g_bufB[(size_t)gr * OUT + c0 + j] = v;
                if (POOL) colsum[j] += v;
            }
        }
    }
    if (POOL) {
        __syncthreads();
#pragma unroll
        for (int j = 0; j < C; j++) atomicAdd(&spool[c0 + j], colsum[j]);
        __syncthreads();
        if (t < OUT) atomicAdd(&g_pool[t], spool[t]);
    }
}

// -------- vectorized SpMM --------
// out[i, :] = (optional relu/bias)( sum_e val * src[col(e), :] )
// G lanes per node; each active lane handles one float4 of the feature row.
// SRC_A: read g_bufA write g_bufB, else read g_bufB write g_bufA.
template <int F, int G, bool BIASRELU, bool SRC_A>
__global__ void spmm_kernel(const float* __restrict__ bias) {
    constexpr int GPB = 256 / G;
    int g = blockIdx.x * GPB + threadIdx.x / G;
    int lane = threadIdx.x % G;
    if (g >= NN) return;
    bool active = (lane * 4 < F);

    const float4* __restrict__ src = (const float4*)(SRC_A ? g_bufA : g_bufB);
    float* __restrict__ dst = SRC_A ? g_bufB : g_bufA;

    int s = g_rowptr[g];
    int e = g_rowptr[g + 1];
    float4 acc = make_float4(0.f, 0.f, 0.f, 0.f);
    for (int i = s; i < e; i++) {
        int2 m = __ldg(&g_edge[i]);
        float v = __int_as_float(m.y);
        if (active) {
            float4 sv = __ldg(&src[(size_t)m.x * (F / 4) + lane]);
            acc.x += v * sv.x;
            acc.y += v * sv.y;
            acc.z += v * sv.z;
            acc.w += v * sv.w;
        }
    }
    if (active) {
        if (BIASRELU) {
            float4 b = *(const float4*)&bias[lane * 4];
            acc.x = fmaxf(acc.x + b.x, 0.f);
            acc.y = fmaxf(acc.y + b.y, 0.f);
            acc.z = fmaxf(acc.z + b.z, 0.f);
            acc.w = fmaxf(acc.w + b.w, 0.f);
        }
        *(float4*)&dst[(size_t)g * F + lane * 4] = acc;
    }
}

// -------- head: mean -> fc1+relu -> fc2 -> softmax --------
__global__ void head_kernel(const float* __restrict__ f1W, const float* __restrict__ f1b,
                            const float* __restrict__ f2W, const float* __restrict__ f2b,
                            float* __restrict__ out) {
    __shared__ float y[64];
    __shared__ float a[32];
    __shared__ float l[2];
    int t = threadIdx.x;
    y[t] = g_pool[t] * (1.0f / NN);
    __syncthreads();
    if (t < 32) {
        float s = f1b[t];
#pragma unroll
        for (int k = 0; k < 64; k++) s += y[k] * f1W[k * 32 + t];
        a[t] = fmaxf(s, 0.f);
    }
    __syncthreads();
    if (t < 2) {
        float s = f2b[t];
#pragma unroll
        for (int j = 0; j < 32; j++) s += a[j] * f2W[j * 2 + t];
        l[t] = s;
    }
    __syncthreads();
    if (t == 0) {
        float m = fmaxf(l[0], l[1]);
        float e0 = expf(l[0] - m), e1 = expf(l[1] - m);
        float inv = 1.0f / (e0 + e1);
        out[0] = e0 * inv;
        out[1] = e1 * inv;
    }
}

extern "C" void kernel_launch(void* const* d_in, const int* in_sizes, int n_in,
                              void* d_out, int out_size) {
    (void)in_sizes; (void)n_in; (void)out_size;
    const float* x   = (const float*)d_in[0];
    const int*   row = (const int*)d_in[1];
    const int*   col = (const int*)d_in[2];
    const float* ev  = (const float*)d_in[3];
    const float* W1  = (const float*)d_in[4];
    const float* b1  = (const float*)d_in[5];
    const float* W2  = (const float*)d_in[6];
    const float* b2  = (const float*)d_in[7];
    const float* W3  = (const float*)d_in[8];
    const float* b3  = (const float*)d_in[9];
    const float* f1W = (const float*)d_in[10];
    const float* f1b = (const float*)d_in[11];
    const float* f2W = (const float*)d_in[12];
    const float* f2b = (const float*)d_in[13];
    float* out = (float*)d_out;

    const int EB = (NE + 255) / 256;   // 6250
    const int GB = (NN + 127) / 128;   // 782

    // CSR build
    init_kernel<<<(NN + 255) / 256, 256>>>();
    hist_kernel<<<EB, 256>>>(row);
    scan_phase1<<<98, 1024>>>();
    scan_phase2<<<1, 128>>>();
    scan_phase3<<<98, 1024>>>();
    scatter_kernel<<<EB, 256>>>(row, col, ev);

    // Layer 1: A = x@W1 ; B = relu(spmm(A)+b1)        [F=32]
    gemm1_kernel<<<GB, 256>>>(x, W1);
    spmm_kernel<32, 8, true, true><<<(NN + 31) / 32, 256>>>(b1);

    // Layer 2: A = spmm(B) [F=32] ; B = relu(A@W2+b2) [N,48]
    spmm_kernel<32, 8, false, false><<<(NN + 31) / 32, 256>>>(nullptr);
    gemm_small_kernel<32, 48, false><<<GB, 256>>>(W2, b2);

    // Layer 3: A = spmm(B) [F=48] ; B = relu(A@W3+b3) [N,64] + fused pool
    spmm_kernel<48, 16, false, false><<<(NN + 15) / 16, 256>>>(nullptr);
    gemm_small_kernel<48, 64, true><<<GB, 256>>>(W3, b3);

    // Head
    head_kernel<<<1, 64>>>(f1W, f1b, f2W, f2b, out);
}